// round 3
// baseline (speedup 1.0000x reference)
#include <cuda_runtime.h>
#include <math.h>
#include <stdint.h>

// Problem constants
#define Nn   4096
#define KK   8
#define FD   512
#define NFW  532          // 512 + 4 + 16
#define EAW  1029         // 5 + 2*512
#define NKE  (Nn*KK)      // 32768

#define NB   148          // persistent blocks (== #SMs, guaranteed resident)
#define NT   1024

// Output layout (flattened float32 concat of the tuple)
#define NF_OFF   ((size_t)0)
#define EI_OFF   ((size_t)Nn*NFW)                 // 2179072
#define EA_OFF   (EI_OFF + (size_t)2*NKE)         // 2244608
#define OCC_OFF  (EA_OFF + (size_t)NKE*EAW)       // 35962880
#define MASK_OFF (OCC_OFF + (size_t)Nn)           // 35966976

#define DIST_T   108.0f
#define DIST_T2  11666.0f
#define SENT_D   1e30f
#define SENT_I   0x7fffffff

__device__ float4   g_xywh[Nn];
__device__ int      g_dst [NKE];
__device__ float    g_nbd [NKE];
__device__ unsigned g_cnt = 0;
__device__ unsigned g_gen = 0;

// ---------------------------------------------------------------------------
// Grid-wide barrier (all NB blocks are co-resident by construction).
// ---------------------------------------------------------------------------
__device__ __forceinline__ void gridbar()
{
    __syncthreads();
    if (threadIdx.x == 0) {
        __threadfence();
        unsigned gen = *((volatile unsigned*)&g_gen);   // read BEFORE arriving
        unsigned t = atomicAdd(&g_cnt, 1);
        if (t == NB - 1) {
            g_cnt = 0;
            __threadfence();
            atomicAdd(&g_gen, 1);
        } else {
            while (*((volatile unsigned*)&g_gen) == gen) { __nanosleep(64); }
        }
        __threadfence();
    }
    __syncthreads();
}

// ---------------------------------------------------------------------------
__global__ void __launch_bounds__(NT, 1)
fused(const float* __restrict__ reid, const float* __restrict__ pos, float* out)
{
    __shared__ float4 s_pool[2048];       // 32 KB, reused across phases
    __shared__ float  s_head[KK * 5];
    __shared__ float  s_m[KK];
    __shared__ int    s_dsti[KK];

    int tid  = threadIdx.x;
    int warp = tid >> 5, lane = tid & 31;

    // ======================== Phase A: xywh + reid norm ====================
    {
        int gt = blockIdx.x * NT + tid;
        if (gt < Nn) {
            float x1 = pos[gt*4+0], y1 = pos[gt*4+1], x2 = pos[gt*4+2], y2 = pos[gt*4+3];
            float cx = 0.5f*(x1+x2), cy = 0.5f*(y1+y2);
            float w = x2 - x1, h = y2 - y1;
            g_xywh[gt] = make_float4(cx, cy, w, h);
            float* o = out + (size_t)gt * NFW;
            o[512] = cx / 1920.0f;
            o[513] = cy / 1080.0f;
            o[514] = w  / 1920.0f;
            o[515] = h  / 1080.0f;
        }
        int gw = blockIdx.x * 32 + warp;   // one warp per row
        if (gw < Nn) {
            const float4* r = (const float4*)(reid + (size_t)gw * FD);
            float4 v[4];
            float s = 0.0f;
#pragma unroll
            for (int u = 0; u < 4; u++) {
                v[u] = r[lane + 32*u];
                s += v[u].x*v[u].x + v[u].y*v[u].y + v[u].z*v[u].z + v[u].w*v[u].w;
            }
#pragma unroll
            for (int o = 16; o > 0; o >>= 1) s += __shfl_xor_sync(0xffffffffu, s, o);
            float inv = 1.0f / (sqrtf(s) + 1e-12f);
            float4* o4 = (float4*)(out + (size_t)gw * NFW);
#pragma unroll
            for (int u = 0; u < 4; u++) {
                float4 w = v[u];
                w.x *= inv; w.y *= inv; w.z *= inv; w.w *= inv;
                o4[lane + 32*u] = w;
            }
        }
    }
    gridbar();

    // ======================== Phase B: KNN + topology ======================
    {
        float2* sc = (float2*)s_pool;      // 4096 centers
        for (int j = tid; j < Nn; j += NT) {
            float4 q = g_xywh[j];
            sc[j] = make_float2(q.x, q.y);
        }
        __syncthreads();

        int i = blockIdx.x * 32 + warp;
        if (i < Nn) {
            float2 ci = sc[i];
            float dist[KK]; int idx[KK];
#pragma unroll
            for (int u = 0; u < KK; u++) { dist[u] = SENT_D; idx[u] = SENT_I; }

            for (int j = lane; j < Nn; j += 32) {
                float dx = ci.x - sc[j].x;
                float dy = ci.y - sc[j].y;
                float d2 = dx*dx + dy*dy;
                if (j != i && d2 <= DIST_T2) {
                    float Dv = sqrtf(fmaxf(d2, 1e-12f));
                    if (Dv <= DIST_T) {
                        float kd = Dv; int ki = j;
#pragma unroll
                        for (int u = 0; u < KK; u++) {
                            bool sw = (kd < dist[u]) || (kd == dist[u] && ki < idx[u]);
                            if (sw) {
                                float td = dist[u]; int ti = idx[u];
                                dist[u] = kd; idx[u] = ki;
                                kd = td; ki = ti;
                            }
                        }
                    }
                }
            }

            // warp merge: 8 rounds of packed (distBits, idx) min-reduce
            float res_d[KK]; int res_i[KK];
#pragma unroll
            for (int k = 0; k < KK; k++) {
                unsigned long long key =
                    ((unsigned long long)__float_as_uint(dist[0]) << 32) | (unsigned)idx[0];
#pragma unroll
                for (int o = 16; o > 0; o >>= 1) {
                    unsigned long long other = __shfl_xor_sync(0xffffffffu, key, o);
                    if (other < key) key = other;
                }
                res_d[k] = __uint_as_float((unsigned)(key >> 32));
                res_i[k] = (int)(unsigned)(key & 0xffffffffull);
                unsigned long long mine =
                    ((unsigned long long)__float_as_uint(dist[0]) << 32) | (unsigned)idx[0];
                if (mine == key) {
#pragma unroll
                    for (int u = 0; u < KK-1; u++) { dist[u] = dist[u+1]; idx[u] = idx[u+1]; }
                    dist[KK-1] = SENT_D; idx[KK-1] = SENT_I;
                }
            }

            if (lane == 0) {
                bool val[KK]; int ni[KK]; float nd[KK];
                float vx[KK], vy[KK];
#pragma unroll
                for (int k = 0; k < KK; k++) {
                    val[k] = res_d[k] < 1e9f;
                    ni[k]  = val[k] ? res_i[k] : 0;
                    nd[k]  = val[k] ? res_d[k] : 0.0f;
                    float2 cn = sc[ni[k]];
                    vx[k] = cn.x - ci.x;
                    vy[k] = cn.y - ci.y;
                    g_dst[i*KK + k] = ni[k];
                    g_nbd[i*KK + k] = val[k] ? res_d[k] : SENT_D;
                }
                float* nf = out + (size_t)i * NFW;
#pragma unroll
                for (int k = 0; k < KK; k++) nf[516 + k] = nd[k] / 1080.0f;

                const float LO = (float)(-1.0 + 1e-6);
                const float HI = (float)( 1.0 - 1e-6);
#pragma unroll
                for (int k = 0; k < KK-1; k++) {
                    float a = 0.0f;
                    if (val[k+1]) {
                        float dot = vx[k]*vx[k+1] + vy[k]*vy[k+1];
                        float n1 = sqrtf(vx[k]*vx[k] + vy[k]*vy[k]);
                        float n2 = sqrtf(vx[k+1]*vx[k+1] + vy[k+1]*vy[k+1]);
                        float cs = dot / (n1*n2 + 1e-12f);
                        cs = fminf(fmaxf(cs, LO), HI);
                        a = acosf(cs) * 57.29577951308232f;
                    }
                    nf[524 + k] = a / 360.0f;
                }
                nf[531] = 0.0f;

                float occf = 0.0f;
                if (val[0]) {
                    int nn = ni[0];
                    float xi1 = pos[i*4+0],  yi1 = pos[i*4+1];
                    float xi2 = pos[i*4+2],  yi2 = pos[i*4+3];
                    float xn1 = pos[nn*4+0], yn1 = pos[nn*4+1];
                    float xn2 = pos[nn*4+2], yn2 = pos[nn*4+3];
                    float ox = fminf(xi2, xn2) - fmaxf(xi1, xn1);
                    float oy = fminf(yi2, yn2) - fmaxf(yi1, yn1);
                    float ov = fmaxf(ox, 0.0f) * fmaxf(oy, 0.0f);
                    float w = xi2 - xi1, h = yi2 - yi1;
                    occf = (ov > w*h*0.5f) ? 1.0f : 0.0f;
                }
                out[OCC_OFF + i] = occf;
            }
        }
    }
    gridbar();

    // ======================== Phase C: edge features =======================
    {
        float* s_src = (float*)s_pool;     // 512 floats (src reid)
        const float* nfc = out;

        for (int i = blockIdx.x; i < Nn; i += NB) {
            if (tid < 128)
                ((float4*)s_src)[tid] = ((const float4*)(nfc + (size_t)i * NFW))[tid];

            if (tid < KK) {
                int k = tid, e = i*KK + k;
                int dst = g_dst[e];
                float m = (g_nbd[e] < 1e9f) ? 1.0f : 0.0f;

                float4 xi  = g_xywh[i];
                float4 xd4 = g_xywh[dst];
                float xd = (xi.x - xd4.x) / 1920.0f;
                float yd = (xi.y - xd4.y) / 1080.0f;

                float pi0 = pos[i*4+0],   pi1 = pos[i*4+1];
                float pi2 = pos[i*4+2],   pi3 = pos[i*4+3];
                float pd0 = pos[dst*4+0], pd1 = pos[dst*4+1];
                float pd2 = pos[dst*4+2], pd3 = pos[dst*4+3];
                float ix1 = fmaxf(pi0, pd0), iy1 = fmaxf(pi1, pd1);
                float ix2 = fminf(pi2, pd2), iy2 = fminf(pi3, pd3);
                float inter = fmaxf(ix2-ix1, 0.0f) * fmaxf(iy2-iy1, 0.0f);
                float ai = (pi2-pi0)*(pi3-pi1);
                float ad = (pd2-pd0)*(pd3-pd1);
                float iou = inter / (ai + ad - inter + 1e-12f);
                float lw = logf(xi.z / xd4.z);
                float lh = logf(xi.w / xd4.w);

                s_head[k*5+0] = xd  * m;
                s_head[k*5+1] = yd  * m;
                s_head[k*5+2] = iou * m;
                s_head[k*5+3] = lw  * m;
                s_head[k*5+4] = lh  * m;
                s_m[k]    = m;
                s_dsti[k] = dst;

                out[EI_OFF + e]       = (float)i;
                out[EI_OFF + NKE + e] = (float)dst;
                out[MASK_OFF + e]     = m;
            }
            __syncthreads();

#pragma unroll
            for (int k = 0; k < KK; k++) {
                int e = i*KK + k;
                float m = s_m[k];
                int dst = s_dsti[k];
                float* ea = out + EA_OFF + (size_t)e * EAW;

                float v;
                if (tid < 512) v = s_src[tid];
                else           v = __ldg(nfc + (size_t)dst * NFW + (tid - 512));
                __stcs(ea + 5 + tid, v * m);
                if (tid < 5) ea[tid] = s_head[k*5 + tid];
            }
            __syncthreads();   // before next node overwrites s_src
        }
    }
}

// ---------------------------------------------------------------------------
extern "C" void kernel_launch(void* const* d_in, const int* in_sizes, int n_in,
                              void* d_out, int out_size)
{
    const float* reid = (const float*)d_in[0];
    const float* pos  = (const float*)d_in[1];
    float* out = (float*)d_out;

    fused<<<NB, NT>>>(reid, pos, out);
}

// round 4
// speedup vs baseline: 1.5761x; 1.5761x over previous
#include <cuda_runtime.h>
#include <math.h>
#include <stdint.h>

// Problem constants
#define Nn   4096
#define KK   8
#define FD   512
#define NFW  532          // 512 + 4 + 16
#define EAW  1029         // 5 + 2*512
#define NKE  (Nn*KK)      // 32768

// Output layout (flattened float32 concat of the tuple)
#define NF_OFF   ((size_t)0)
#define EI_OFF   ((size_t)Nn*NFW)                 // 2179072
#define EA_OFF   (EI_OFF + (size_t)2*NKE)         // 2244608
#define OCC_OFF  (EA_OFF + (size_t)NKE*EAW)       // 35962880
#define MASK_OFF (OCC_OFF + (size_t)Nn)           // 35966976

#define DIST_T   108.0f
#define DIST_T2  11666.0f
#define SENT_D   1e30f
#define SENT_I   0x7fffffff

__device__ float4 g_xywh[Nn];
__device__ int    g_dst [NKE];
__device__ float  g_nbd [NKE];

// ---------------------------------------------------------------------------
// K1: reid L2-normalize + pos_normed + xywh stash. One warp per row.
// ---------------------------------------------------------------------------
__global__ void k_norm(const float* __restrict__ reid,
                       const float* __restrict__ pos,
                       float* out)
{
    int warp = threadIdx.x >> 5, lane = threadIdx.x & 31;
    int i = blockIdx.x * 8 + warp;

    const float4* r = (const float4*)(reid + (size_t)i * FD);
    float4 v[4];
    float s = 0.0f;
#pragma unroll
    for (int u = 0; u < 4; u++) {
        v[u] = r[lane + 32*u];
        s += v[u].x*v[u].x + v[u].y*v[u].y + v[u].z*v[u].z + v[u].w*v[u].w;
    }
#pragma unroll
    for (int o = 16; o > 0; o >>= 1) s += __shfl_xor_sync(0xffffffffu, s, o);
    float inv = 1.0f / (sqrtf(s) + 1e-12f);

    float4* o4 = (float4*)(out + (size_t)i * NFW);
#pragma unroll
    for (int u = 0; u < 4; u++) {
        float4 w = v[u];
        w.x *= inv; w.y *= inv; w.z *= inv; w.w *= inv;
        o4[lane + 32*u] = w;
    }

    if (lane == 0) {
        float x1 = pos[i*4+0], y1 = pos[i*4+1], x2 = pos[i*4+2], y2 = pos[i*4+3];
        float cx = 0.5f*(x1+x2), cy = 0.5f*(y1+y2);
        float w = x2 - x1, h = y2 - y1;
        g_xywh[i] = make_float4(cx, cy, w, h);
        float* o = out + (size_t)i * NFW;
        o[512] = cx / 1920.0f;
        o[513] = cy / 1080.0f;
        o[514] = w  / 1920.0f;
        o[515] = h  / 1080.0f;
    }
}

// ---------------------------------------------------------------------------
// K2: per-row KNN (one warp per row), topology features, occ, stash edges.
// ---------------------------------------------------------------------------
__global__ void k_knn(const float* __restrict__ pos, float* out)
{
    __shared__ float2 sc[Nn];      // 32 KB of centers
    int t = threadIdx.x;           // 256 threads = 8 warps
    for (int j = t; j < Nn; j += 256) {
        float4 q = g_xywh[j];
        sc[j] = make_float2(q.x, q.y);
    }
    __syncthreads();

    int warp = t >> 5, lane = t & 31;
    int i = blockIdx.x * 8 + warp;
    float2 ci = sc[i];

    float dist[KK]; int idx[KK];
#pragma unroll
    for (int u = 0; u < KK; u++) { dist[u] = SENT_D; idx[u] = SENT_I; }

    for (int j = lane; j < Nn; j += 32) {
        float dx = ci.x - sc[j].x;
        float dy = ci.y - sc[j].y;
        float d2 = dx*dx + dy*dy;
        if (j != i && d2 <= DIST_T2) {
            float Dv = sqrtf(fmaxf(d2, 1e-12f));
            if (Dv <= DIST_T) {
                float kd = Dv; int ki = j;
#pragma unroll
                for (int u = 0; u < KK; u++) {
                    bool sw = (kd < dist[u]) || (kd == dist[u] && ki < idx[u]);
                    if (sw) {
                        float td = dist[u]; int ti = idx[u];
                        dist[u] = kd; idx[u] = ki;
                        kd = td; ki = ti;
                    }
                }
            }
        }
    }

    float res_d[KK]; int res_i[KK];
#pragma unroll
    for (int k = 0; k < KK; k++) {
        unsigned long long key =
            ((unsigned long long)__float_as_uint(dist[0]) << 32) | (unsigned)idx[0];
#pragma unroll
        for (int o = 16; o > 0; o >>= 1) {
            unsigned long long other = __shfl_xor_sync(0xffffffffu, key, o);
            if (other < key) key = other;
        }
        res_d[k] = __uint_as_float((unsigned)(key >> 32));
        res_i[k] = (int)(unsigned)(key & 0xffffffffull);
        unsigned long long mine =
            ((unsigned long long)__float_as_uint(dist[0]) << 32) | (unsigned)idx[0];
        if (mine == key) {
#pragma unroll
            for (int u = 0; u < KK-1; u++) { dist[u] = dist[u+1]; idx[u] = idx[u+1]; }
            dist[KK-1] = SENT_D; idx[KK-1] = SENT_I;
        }
    }

    if (lane == 0) {
        bool val[KK]; int ni[KK]; float nd[KK];
        float vx[KK], vy[KK];
#pragma unroll
        for (int k = 0; k < KK; k++) {
            val[k] = res_d[k] < 1e9f;
            ni[k]  = val[k] ? res_i[k] : 0;
            nd[k]  = val[k] ? res_d[k] : 0.0f;
            float2 cn = sc[ni[k]];
            vx[k] = cn.x - ci.x;
            vy[k] = cn.y - ci.y;
            g_dst[i*KK + k] = ni[k];
            g_nbd[i*KK + k] = val[k] ? res_d[k] : SENT_D;
        }
        float* nf = out + (size_t)i * NFW;
#pragma unroll
        for (int k = 0; k < KK; k++) nf[516 + k] = nd[k] / 1080.0f;

        const float LO = (float)(-1.0 + 1e-6);
        const float HI = (float)( 1.0 - 1e-6);
#pragma unroll
        for (int k = 0; k < KK-1; k++) {
            float a = 0.0f;
            if (val[k+1]) {
                float dot = vx[k]*vx[k+1] + vy[k]*vy[k+1];
                float n1 = sqrtf(vx[k]*vx[k] + vy[k]*vy[k]);
                float n2 = sqrtf(vx[k+1]*vx[k+1] + vy[k+1]*vy[k+1]);
                float cs = dot / (n1*n2 + 1e-12f);
                cs = fminf(fmaxf(cs, LO), HI);
                a = acosf(cs) * 57.29577951308232f;
            }
            nf[524 + k] = a / 360.0f;
        }
        nf[531] = 0.0f;

        float occf = 0.0f;
        if (val[0]) {
            int nn = ni[0];
            float xi1 = pos[i*4+0],  yi1 = pos[i*4+1];
            float xi2 = pos[i*4+2],  yi2 = pos[i*4+3];
            float xn1 = pos[nn*4+0], yn1 = pos[nn*4+1];
            float xn2 = pos[nn*4+2], yn2 = pos[nn*4+3];
            float ox = fminf(xi2, xn2) - fmaxf(xi1, xn1);
            float oy = fminf(yi2, yn2) - fmaxf(yi1, yn1);
            float ov = fmaxf(ox, 0.0f) * fmaxf(oy, 0.0f);
            float w = xi2 - xi1, h = yi2 - yi1;
            occf = (ov > w*h*0.5f) ? 1.0f : 0.0f;
        }
        out[OCC_OFF + i] = occf;
    }
}

// ---------------------------------------------------------------------------
// K3: edge features. ONE WARP PER EDGE, fully unrolled, no smem, no syncs.
//     Max MLP: 16 independent loads in flight per thread-step.
// ---------------------------------------------------------------------------
__global__ void __launch_bounds__(256)
k_edge(const float* __restrict__ pos, float* __restrict__ out)
{
    int warp = threadIdx.x >> 5, lane = threadIdx.x & 31;
    int e = blockIdx.x * 8 + warp;          // 32768 warps over 4096 blocks
    int i = e >> 3;

    int   dst = g_dst[e];
    float m   = (g_nbd[e] < 1e9f) ? 1.0f : 0.0f;

    const float* rs = out + (size_t)i   * NFW;   // src reid (L2-resident)
    const float* rd = out + (size_t)dst * NFW;   // dst reid
    float* ea = out + EA_OFF + (size_t)e * EAW;

    // ---- bulk reid copy: 2 x 16 unrolled iterations, streaming stores ----
#pragma unroll
    for (int u = 0; u < 16; u++) {
        float v = __ldg(rs + u*32 + lane);
        __stcs(ea + 5 + u*32 + lane, v * m);
    }
#pragma unroll
    for (int u = 0; u < 16; u++) {
        float v = __ldg(rd + u*32 + lane);
        __stcs(ea + 517 + u*32 + lane, v * m);
    }

    // ---- scalar head features (computed uniformly; lane 0 stores) ----
    float4 xi  = g_xywh[i];
    float4 xd4 = g_xywh[dst];

    if (lane < 8) {   // one warp-fragment does the scalar tail work
        if (lane == 0) {
            float xd = (xi.x - xd4.x) / 1920.0f;
            float yd = (xi.y - xd4.y) / 1080.0f;

            float pi0 = pos[i*4+0],   pi1 = pos[i*4+1];
            float pi2 = pos[i*4+2],   pi3 = pos[i*4+3];
            float pd0 = pos[dst*4+0], pd1 = pos[dst*4+1];
            float pd2 = pos[dst*4+2], pd3 = pos[dst*4+3];
            float ix1 = fmaxf(pi0, pd0), iy1 = fmaxf(pi1, pd1);
            float ix2 = fminf(pi2, pd2), iy2 = fminf(pi3, pd3);
            float inter = fmaxf(ix2-ix1, 0.0f) * fmaxf(iy2-iy1, 0.0f);
            float ai = (pi2-pi0)*(pi3-pi1);
            float ad = (pd2-pd0)*(pd3-pd1);
            float iou = inter / (ai + ad - inter + 1e-12f);
            float lw = logf(xi.z / xd4.z);
            float lh = logf(xi.w / xd4.w);

            ea[0] = xd  * m;
            ea[1] = yd  * m;
            ea[2] = iou * m;
            ea[3] = lw  * m;
            ea[4] = lh  * m;

            out[EI_OFF + e]       = (float)i;
            out[EI_OFF + NKE + e] = (float)dst;
            out[MASK_OFF + e]     = m;
        }
    }
}

// ---------------------------------------------------------------------------
extern "C" void kernel_launch(void* const* d_in, const int* in_sizes, int n_in,
                              void* d_out, int out_size)
{
    const float* reid = (const float*)d_in[0];
    const float* pos  = (const float*)d_in[1];
    float* out = (float*)d_out;

    k_norm<<<Nn/8, 256>>>(reid, pos, out);
    k_knn <<<Nn/8, 256>>>(pos, out);
    k_edge<<<NKE/8, 256>>>(pos, out);
}